// round 10
// baseline (speedup 1.0000x reference)
#include <cuda_runtime.h>

#define LRDIM 512
#define HRDIM 2048
#define NIMG  12          // 4 batch * 3 channels
#define EPSF  0.01f

// Scratch: mean_A and mean_b at LR resolution (12 * 512 * 512 floats each).
__device__ float g_mA[NIMG * LRDIM * LRDIM];
__device__ float g_mB[NIMG * LRDIM * LRDIM];

// ---------------------------------------------------------------------------
// Kernel 1: fused LR pipeline.
// Per 32x32 output tile:
//   load 36x36 x/y tile (halo 2, edge-replicated),
//   compute A,b on a 34x34 region (halo 1). For positions whose global A-coord
//   is outside the image, compute A at the CLAMPED position — this reproduces
//   edge-replication padding of A/b exactly.
//   3x3 box over A,b -> mean_A, mean_b written to global scratch.
// ---------------------------------------------------------------------------
__global__ __launch_bounds__(256) void lr_kernel(const float* __restrict__ x,
                                                 const float* __restrict__ y) {
    const int img = blockIdx.z;
    const int bx  = blockIdx.x * 32;
    const int by  = blockIdx.y * 32;
    const int tid = threadIdx.x;

    const float* xp = x + (size_t)img * LRDIM * LRDIM;
    const float* yp = y + (size_t)img * LRDIM * LRDIM;

    __shared__ float sx[36 * 36];
    __shared__ float sy[36 * 36];
    __shared__ float sA[34 * 34];
    __shared__ float sB[34 * 34];

    // Load 36x36 input tile covering global rows/cols [b-2, b+33], clamped.
    for (int i = tid; i < 36 * 36; i += 256) {
        int r  = i / 36, c = i % 36;
        int gr = min(max(by - 2 + r, 0), LRDIM - 1);
        int gc = min(max(bx - 2 + c, 0), LRDIM - 1);
        sx[i] = xp[gr * LRDIM + gc];
        sy[i] = yp[gr * LRDIM + gc];
    }
    __syncthreads();

    const float inv9 = 1.0f / 9.0f;

    // A,b on 34x34 region: local (r,c) -> global (by-1+r, bx-1+c), clamped.
    for (int i = tid; i < 34 * 34; i += 256) {
        int r  = i / 34, c = i % 34;
        int ar = min(max(by - 1 + r, 0), LRDIM - 1) - (by - 2);  // shared row of center
        int ac = min(max(bx - 1 + c, 0), LRDIM - 1) - (bx - 2);  // shared col of center
        float s1 = 0.f, s2 = 0.f, s3 = 0.f, s4 = 0.f;
        #pragma unroll
        for (int dr = -1; dr <= 1; ++dr) {
            #pragma unroll
            for (int dc = -1; dc <= 1; ++dc) {
                float xv = sx[(ar + dr) * 36 + (ac + dc)];
                float yv = sy[(ar + dr) * 36 + (ac + dc)];
                s1 += xv;
                s2 += yv;
                s3 += xv * yv;
                s4 += xv * xv;
            }
        }
        float mx  = s1 * inv9;
        float my  = s2 * inv9;
        float cov = s3 * inv9 - mx * my;
        float var = s4 * inv9 - mx * mx;
        float A   = cov / (var + EPSF);
        sA[i] = A;
        sB[i] = my - A * mx;
    }
    __syncthreads();

    float* mA = g_mA + (size_t)img * LRDIM * LRDIM;
    float* mB = g_mB + (size_t)img * LRDIM * LRDIM;

    // 3x3 box over A,b -> 32x32 outputs.
    for (int i = tid; i < 32 * 32; i += 256) {
        int r = i / 32, c = i % 32;
        float a = 0.f, b = 0.f;
        #pragma unroll
        for (int dr = 0; dr < 3; ++dr) {
            #pragma unroll
            for (int dc = 0; dc < 3; ++dc) {
                a += sA[(r + dr) * 34 + (c + dc)];
                b += sB[(r + dr) * 34 + (c + dc)];
            }
        }
        int go = (by + r) * LRDIM + (bx + c);
        mA[go] = a * inv9;
        mB[go] = b * inv9;
    }
}

// ---------------------------------------------------------------------------
// Kernel 2: HR apply. One block per (HR row, image).
// Row-lerped mean_A / mean_b are staged in shared (hoists the row interp),
// then each thread does column lerp + clip(A*x + b) for 8 pixels via float4.
// ---------------------------------------------------------------------------
__global__ __launch_bounds__(256) void hr_kernel(const float* __restrict__ xhr,
                                                 float* __restrict__ out) {
    const int row = blockIdx.x;
    const int img = blockIdx.y;
    const int tid = threadIdx.x;
    const float scale = (float)(LRDIM - 1) / (float)(HRDIM - 1);  // 511/2047

    float pr = (float)row * scale;
    int   r0 = (int)pr;                 // floor (pr >= 0)
    float tr = pr - (float)r0;
    int   r1 = min(r0 + 1, LRDIM - 1);

    __shared__ float sA[LRDIM + 1];
    __shared__ float sB[LRDIM + 1];

    const float* mA = g_mA + (size_t)img * LRDIM * LRDIM;
    const float* mB = g_mB + (size_t)img * LRDIM * LRDIM;

    for (int c = tid; c < LRDIM; c += 256) {
        float a0 = mA[r0 * LRDIM + c];
        float a1 = mA[r1 * LRDIM + c];
        float b0 = mB[r0 * LRDIM + c];
        float b1 = mB[r1 * LRDIM + c];
        float av = a0 + (a1 - a0) * tr;
        float bv = b0 + (b1 - b0) * tr;
        sA[c] = av;
        sB[c] = bv;
        if (c == LRDIM - 1) {            // sentinel so c0+1 never branches
            sA[LRDIM] = av;
            sB[LRDIM] = bv;
        }
    }
    __syncthreads();

    const float4* xrow = (const float4*)(xhr + ((size_t)img * HRDIM + row) * HRDIM);
    float4*       orow = (float4*)(out + ((size_t)img * HRDIM + row) * HRDIM);

    #pragma unroll
    for (int half = 0; half < 2; ++half) {
        int    c4 = half * 1024 + tid * 4;
        float4 xv = xrow[c4 >> 2];
        float  xin[4] = {xv.x, xv.y, xv.z, xv.w};
        float  o[4];
        #pragma unroll
        for (int k = 0; k < 4; ++k) {
            int   c  = c4 + k;
            float pc = (float)c * scale;
            int   c0 = (int)pc;
            float tc = pc - (float)c0;
            float a0 = sA[c0];
            float A  = a0 + (sA[c0 + 1] - a0) * tc;
            float b0 = sB[c0];
            float B  = b0 + (sB[c0 + 1] - b0) * tc;
            o[k] = fminf(fmaxf(fmaf(A, xin[k], B), 0.0f), 255.0f);
        }
        orow[c4 >> 2] = make_float4(o[0], o[1], o[2], o[3]);
    }
}

extern "C" void kernel_launch(void* const* d_in, const int* in_sizes, int n_in,
                              void* d_out, int out_size) {
    const float* x_lr = (const float*)d_in[0];
    const float* y_lr = (const float*)d_in[1];
    const float* x_hr = (const float*)d_in[2];
    float*       out  = (float*)d_out;

    dim3 g1(LRDIM / 32, LRDIM / 32, NIMG);
    lr_kernel<<<g1, 256>>>(x_lr, y_lr);

    dim3 g2(HRDIM, NIMG);
    hr_kernel<<<g2, 256>>>(x_hr, out);
}

// round 12
// speedup vs baseline: 1.0052x; 1.0052x over previous
#include <cuda_runtime.h>

#define LRDIM 512
#define HRDIM 2048
#define NIMG  12          // 4 batch * 3 channels
#define EPSF  0.01f

// Scratch: mean_A and mean_b at LR resolution (12 * 512 * 512 floats each).
__device__ float g_mA[NIMG * LRDIM * LRDIM];
__device__ float g_mB[NIMG * LRDIM * LRDIM];

// ---------------------------------------------------------------------------
// Kernel 1: fused LR pipeline.
// Per 32x32 output tile:
//   load 36x36 x/y tile (halo 2, edge-replicated),
//   compute A,b on a 34x34 region (halo 1). For positions whose global A-coord
//   is outside the image, compute A at the CLAMPED position — this reproduces
//   edge-replication padding of A/b exactly.
//   3x3 box over A,b -> mean_A, mean_b written to global scratch.
// ---------------------------------------------------------------------------
__global__ __launch_bounds__(256) void lr_kernel(const float* __restrict__ x,
                                                 const float* __restrict__ y) {
    const int img = blockIdx.z;
    const int bx  = blockIdx.x * 32;
    const int by  = blockIdx.y * 32;
    const int tid = threadIdx.x;

    const float* xp = x + (size_t)img * LRDIM * LRDIM;
    const float* yp = y + (size_t)img * LRDIM * LRDIM;

    __shared__ float sx[36 * 36];
    __shared__ float sy[36 * 36];
    __shared__ float sA[34 * 34];
    __shared__ float sB[34 * 34];

    // Load 36x36 input tile covering global rows/cols [b-2, b+33], clamped.
    for (int i = tid; i < 36 * 36; i += 256) {
        int r  = i / 36, c = i % 36;
        int gr = min(max(by - 2 + r, 0), LRDIM - 1);
        int gc = min(max(bx - 2 + c, 0), LRDIM - 1);
        sx[i] = xp[gr * LRDIM + gc];
        sy[i] = yp[gr * LRDIM + gc];
    }
    __syncthreads();

    const float inv9 = 1.0f / 9.0f;

    // A,b on 34x34 region: local (r,c) -> global (by-1+r, bx-1+c), clamped.
    for (int i = tid; i < 34 * 34; i += 256) {
        int r  = i / 34, c = i % 34;
        int ar = min(max(by - 1 + r, 0), LRDIM - 1) - (by - 2);  // shared row of center
        int ac = min(max(bx - 1 + c, 0), LRDIM - 1) - (bx - 2);  // shared col of center
        float s1 = 0.f, s2 = 0.f, s3 = 0.f, s4 = 0.f;
        #pragma unroll
        for (int dr = -1; dr <= 1; ++dr) {
            #pragma unroll
            for (int dc = -1; dc <= 1; ++dc) {
                float xv = sx[(ar + dr) * 36 + (ac + dc)];
                float yv = sy[(ar + dr) * 36 + (ac + dc)];
                s1 += xv;
                s2 += yv;
                s3 += xv * yv;
                s4 += xv * xv;
            }
        }
        float mx  = s1 * inv9;
        float my  = s2 * inv9;
        float cov = s3 * inv9 - mx * my;
        float var = s4 * inv9 - mx * mx;
        float A   = cov / (var + EPSF);
        sA[i] = A;
        sB[i] = my - A * mx;
    }
    __syncthreads();

    float* mA = g_mA + (size_t)img * LRDIM * LRDIM;
    float* mB = g_mB + (size_t)img * LRDIM * LRDIM;

    // 3x3 box over A,b -> 32x32 outputs.
    for (int i = tid; i < 32 * 32; i += 256) {
        int r = i / 32, c = i % 32;
        float a = 0.f, b = 0.f;
        #pragma unroll
        for (int dr = 0; dr < 3; ++dr) {
            #pragma unroll
            for (int dc = 0; dc < 3; ++dc) {
                a += sA[(r + dr) * 34 + (c + dc)];
                b += sB[(r + dr) * 34 + (c + dc)];
            }
        }
        int go = (by + r) * LRDIM + (bx + c);
        mA[go] = a * inv9;
        mB[go] = b * inv9;
    }
}

// ---------------------------------------------------------------------------
// Kernel 2: HR apply. One block per (HR row, image).
// Row-lerped mean_A / mean_b are staged in shared (hoists the row interp),
// then each thread does column lerp + clip(A*x + b) for 8 pixels via float4.
// ---------------------------------------------------------------------------
__global__ __launch_bounds__(256) void hr_kernel(const float* __restrict__ xhr,
                                                 float* __restrict__ out) {
    const int row = blockIdx.x;
    const int img = blockIdx.y;
    const int tid = threadIdx.x;
    const float scale = (float)(LRDIM - 1) / (float)(HRDIM - 1);  // 511/2047

    float pr = (float)row * scale;
    int   r0 = (int)pr;                 // floor (pr >= 0)
    float tr = pr - (float)r0;
    int   r1 = min(r0 + 1, LRDIM - 1);

    __shared__ float sA[LRDIM + 1];
    __shared__ float sB[LRDIM + 1];

    const float* mA = g_mA + (size_t)img * LRDIM * LRDIM;
    const float* mB = g_mB + (size_t)img * LRDIM * LRDIM;

    for (int c = tid; c < LRDIM; c += 256) {
        float a0 = mA[r0 * LRDIM + c];
        float a1 = mA[r1 * LRDIM + c];
        float b0 = mB[r0 * LRDIM + c];
        float b1 = mB[r1 * LRDIM + c];
        float av = a0 + (a1 - a0) * tr;
        float bv = b0 + (b1 - b0) * tr;
        sA[c] = av;
        sB[c] = bv;
        if (c == LRDIM - 1) {            // sentinel so c0+1 never branches
            sA[LRDIM] = av;
            sB[LRDIM] = bv;
        }
    }
    __syncthreads();

    const float4* xrow = (const float4*)(xhr + ((size_t)img * HRDIM + row) * HRDIM);
    float4*       orow = (float4*)(out + ((size_t)img * HRDIM + row) * HRDIM);

    #pragma unroll
    for (int half = 0; half < 2; ++half) {
        int    c4 = half * 1024 + tid * 4;
        float4 xv = xrow[c4 >> 2];
        float  xin[4] = {xv.x, xv.y, xv.z, xv.w};
        float  o[4];
        #pragma unroll
        for (int k = 0; k < 4; ++k) {
            int   c  = c4 + k;
            float pc = (float)c * scale;
            int   c0 = (int)pc;
            float tc = pc - (float)c0;
            float a0 = sA[c0];
            float A  = a0 + (sA[c0 + 1] - a0) * tc;
            float b0 = sB[c0];
            float B  = b0 + (sB[c0 + 1] - b0) * tc;
            o[k] = fminf(fmaxf(fmaf(A, xin[k], B), 0.0f), 255.0f);
        }
        orow[c4 >> 2] = make_float4(o[0], o[1], o[2], o[3]);
    }
}

extern "C" void kernel_launch(void* const* d_in, const int* in_sizes, int n_in,
                              void* d_out, int out_size) {
    const float* x_lr = (const float*)d_in[0];
    const float* y_lr = (const float*)d_in[1];
    const float* x_hr = (const float*)d_in[2];
    float*       out  = (float*)d_out;

    dim3 g1(LRDIM / 32, LRDIM / 32, NIMG);
    lr_kernel<<<g1, 256>>>(x_lr, y_lr);

    dim3 g2(HRDIM, NIMG);
    hr_kernel<<<g2, 256>>>(x_hr, out);
}